// round 4
// baseline (speedup 1.0000x reference)
#include <cuda_runtime.h>

// ---------------------------------------------------------------------------
// ChannelAttentionModule (DANet): out = beta * softmax(rowmax(G)-G) @ feat + x
// where G = feat @ feat^T, feat = x.reshape(B, C, H*W).
// B=32, C=512, N=H*W=1024, fp32.
//
// R3 changes vs R2:
//  * A operand stored DUPLICATED in smem ([a,a] pairs) so the FFMA2 broadcast
//    operand comes straight from LDS.128 — removes 16 MOVs per k-step.
//  * Global tile loads hoisted above the barrier (overlap LDG with bar wait).
// ---------------------------------------------------------------------------

#define BDIM 32
#define CDIM 512
#define NDIM 1024

#define BM 128
#define BK 16
#define PADA 260   // dup-A row stride (floats): %4==0 (16B-aligned LDS.128)
#define PADB 132   // B row stride (floats)

// 32 MB scratch for attention scores/weights (static device global: allowed).
__device__ float g_scores[(size_t)BDIM * CDIM * CDIM];

typedef unsigned long long u64;

__device__ __forceinline__ void unpack2(u64 v, float& lo, float& hi) {
    asm("mov.b64 {%0, %1}, %2;" : "=f"(lo), "=f"(hi) : "l"(v));
}
__device__ __forceinline__ u64 fma2(u64 a, u64 b, u64 c) {
    u64 d;
    asm("fma.rn.f32x2 %0, %1, %2, %3;" : "=l"(d) : "l"(a), "l"(b), "l"(c));
    return d;
}

// Shared inner product micro-kernel: 8x8 tile, packed accumulators.
// Asd: duplicated A rows [BK][PADA], Bs: B rows [BK][PADB].
__device__ __forceinline__ void mma_tile(const float (*Asd)[PADA],
                                         const float (*Bs)[PADB],
                                         int m0, int n0, u64 acc[8][4]) {
#pragma unroll
    for (int kk = 0; kk < BK; kk++) {
        const ulonglong2* ap = (const ulonglong2*)&Asd[kk][2 * m0];
        ulonglong2 aq0 = ap[0], aq1 = ap[1], aq2 = ap[2], aq3 = ap[3];
        ulonglong2 bq0 = *(const ulonglong2*)&Bs[kk][n0];
        ulonglong2 bq1 = *(const ulonglong2*)&Bs[kk][n0 + 4];
        u64 ad[8] = {aq0.x, aq0.y, aq1.x, aq1.y, aq2.x, aq2.y, aq3.x, aq3.y};
        u64 bb[4] = {bq0.x, bq0.y, bq1.x, bq1.y};
#pragma unroll
        for (int m = 0; m < 8; m++) {
            acc[m][0] = fma2(ad[m], bb[0], acc[m][0]);
            acc[m][1] = fma2(ad[m], bb[1], acc[m][1]);
            acc[m][2] = fma2(ad[m], bb[2], acc[m][2]);
            acc[m][3] = fma2(ad[m], bb[3], acc[m][3]);
        }
    }
}

// ---------------------------------------------------------------------------
// Stage 1: Gram matrix S[b] = feat[b] @ feat[b]^T   (C x C, K = NDIM)
// Upper-triangular 128x128 tile pairs only; off-diagonal mirrored on write.
// ---------------------------------------------------------------------------
__global__ __launch_bounds__(256, 2)
void gram_kernel(const float* __restrict__ x) {
    const int b = blockIdx.y;
    int p = blockIdx.x;
    int ti = 0;
    while (p >= 4 - ti) { p -= 4 - ti; ti++; }
    const int tj = ti + p;   // ti <= tj

    const float* fa = x + (size_t)b * CDIM * NDIM + (size_t)ti * BM * NDIM;
    const float* fb = x + (size_t)b * CDIM * NDIM + (size_t)tj * BM * NDIM;

    __shared__ __align__(16) float Asd[BK][PADA];
    __shared__ __align__(16) float Bs[BK][PADB];

    const int t  = threadIdx.x;
    const int tx = t & 15, ty = t >> 4;
    const int m0 = ty * 8, n0 = tx * 8;

    // global-load indices (2 float4 per tile per thread)
    const int r0c = (t + 0)   >> 2, c0c = ((t + 0)   & 3) << 2;
    const int r1c = (t + 256) >> 2, c1c = ((t + 256) & 3) << 2;

    u64 acc[8][4];
#pragma unroll
    for (int i = 0; i < 8; i++)
#pragma unroll
        for (int j = 0; j < 4; j++) acc[i][j] = 0ull;

    for (int k0 = 0; k0 < NDIM; k0 += BK) {
        // --- issue global loads first (overlaps the barrier wait) ---
        float4 va0 = *(const float4*)(fa + (size_t)r0c * NDIM + k0 + c0c);
        float4 va1 = *(const float4*)(fa + (size_t)r1c * NDIM + k0 + c1c);
        float4 vb0 = *(const float4*)(fb + (size_t)r0c * NDIM + k0 + c0c);
        float4 vb1 = *(const float4*)(fb + (size_t)r1c * NDIM + k0 + c1c);
        __syncthreads();   // previous tile fully consumed
        // A duplicated: [a,a] pairs, transposed to [k][2c]
        *(float2*)&Asd[c0c + 0][2 * r0c] = make_float2(va0.x, va0.x);
        *(float2*)&Asd[c0c + 1][2 * r0c] = make_float2(va0.y, va0.y);
        *(float2*)&Asd[c0c + 2][2 * r0c] = make_float2(va0.z, va0.z);
        *(float2*)&Asd[c0c + 3][2 * r0c] = make_float2(va0.w, va0.w);
        *(float2*)&Asd[c1c + 0][2 * r1c] = make_float2(va1.x, va1.x);
        *(float2*)&Asd[c1c + 1][2 * r1c] = make_float2(va1.y, va1.y);
        *(float2*)&Asd[c1c + 2][2 * r1c] = make_float2(va1.z, va1.z);
        *(float2*)&Asd[c1c + 3][2 * r1c] = make_float2(va1.w, va1.w);
        // B transposed to [k][c]
        Bs[c0c + 0][r0c] = vb0.x; Bs[c0c + 1][r0c] = vb0.y;
        Bs[c0c + 2][r0c] = vb0.z; Bs[c0c + 3][r0c] = vb0.w;
        Bs[c1c + 0][r1c] = vb1.x; Bs[c1c + 1][r1c] = vb1.y;
        Bs[c1c + 2][r1c] = vb1.z; Bs[c1c + 3][r1c] = vb1.w;
        __syncthreads();
        mma_tile(Asd, Bs, m0, n0, acc);
    }

    float* Cb = g_scores + (size_t)b * CDIM * CDIM;
    const int r0 = ti * BM + m0;
    const int c0 = tj * BM + n0;
#pragma unroll
    for (int m = 0; m < 8; m++) {
        float v[8];
        unpack2(acc[m][0], v[0], v[1]);
        unpack2(acc[m][1], v[2], v[3]);
        unpack2(acc[m][2], v[4], v[5]);
        unpack2(acc[m][3], v[6], v[7]);
        float4* dst = (float4*)(Cb + (size_t)(r0 + m) * CDIM + c0);
        dst[0] = make_float4(v[0], v[1], v[2], v[3]);
        dst[1] = make_float4(v[4], v[5], v[6], v[7]);
        if (ti != tj) {
#pragma unroll
            for (int n = 0; n < 8; n++)
                Cb[(size_t)(c0 + n) * CDIM + (r0 + m)] = v[n];
        }
    }
}

// ---------------------------------------------------------------------------
// Stage 2: in-place softmin normalize each row of S.
// softmax(rowmax - S) == exp(rowmin - S) / sum(exp(rowmin - S)).
// ---------------------------------------------------------------------------
__global__ void softmin_kernel() {
    float* row = g_scores + ((size_t)blockIdx.y * CDIM + blockIdx.x) * CDIM;
    const int t = threadIdx.x;           // 0..127
    const int warp = t >> 5, lane = t & 31;

    float4 v = ((float4*)row)[t];
    float mn = fminf(fminf(v.x, v.y), fminf(v.z, v.w));
#pragma unroll
    for (int o = 16; o > 0; o >>= 1)
        mn = fminf(mn, __shfl_xor_sync(0xffffffffu, mn, o));

    __shared__ float rmin[4], rsum[4];
    if (lane == 0) rmin[warp] = mn;
    __syncthreads();
    mn = fminf(fminf(rmin[0], rmin[1]), fminf(rmin[2], rmin[3]));

    float4 e;
    e.x = __expf(mn - v.x); e.y = __expf(mn - v.y);
    e.z = __expf(mn - v.z); e.w = __expf(mn - v.w);
    float s = e.x + e.y + e.z + e.w;
#pragma unroll
    for (int o = 16; o > 0; o >>= 1)
        s += __shfl_xor_sync(0xffffffffu, s, o);
    if (lane == 0) rsum[warp] = s;
    __syncthreads();
    s = rsum[0] + rsum[1] + rsum[2] + rsum[3];

    const float inv = __frcp_rn(s);
    e.x *= inv; e.y *= inv; e.z *= inv; e.w *= inv;
    ((float4*)row)[t] = e;
}

// ---------------------------------------------------------------------------
// Stage 3: out = beta * (W @ feat) + x     (M=C=512, N=NDIM=1024, K=C=512)
// ---------------------------------------------------------------------------
__global__ __launch_bounds__(256, 2)
void av_kernel(const float* __restrict__ x, const float* __restrict__ beta,
               float* __restrict__ out) {
    const int b    = blockIdx.z;
    const int nblk = blockIdx.x;   // 0..7  (N tiles)
    const int mblk = blockIdx.y;   // 0..3  (M tiles)

    const float* W = g_scores + (size_t)b * CDIM * CDIM + (size_t)mblk * BM * CDIM;
    const float* F = x + (size_t)b * CDIM * NDIM + (size_t)nblk * BM;

    __shared__ __align__(16) float Asd[BK][PADA];
    __shared__ __align__(16) float Bs[BK][PADB];

    const int t  = threadIdx.x;
    const int tx = t & 15, ty = t >> 4;
    const int m0 = ty * 8, n0 = tx * 8;

    // A (W) load indices: transpose+duplicate
    const int r0c = (t + 0)   >> 2, c0c = ((t + 0)   & 3) << 2;
    const int r1c = (t + 256) >> 2, c1c = ((t + 256) & 3) << 2;
    // B (feat) load indices: direct copy [k][n]
    const int k0r = (t + 0)   >> 5, n0r = ((t + 0)   & 31) << 2;
    const int k1r = (t + 256) >> 5, n1r = ((t + 256) & 31) << 2;

    u64 acc[8][4];
#pragma unroll
    for (int i = 0; i < 8; i++)
#pragma unroll
        for (int j = 0; j < 4; j++) acc[i][j] = 0ull;

    for (int k0 = 0; k0 < CDIM; k0 += BK) {
        float4 va0 = *(const float4*)(W + (size_t)r0c * CDIM + k0 + c0c);
        float4 va1 = *(const float4*)(W + (size_t)r1c * CDIM + k0 + c1c);
        float4 vb0 = *(const float4*)(F + (size_t)(k0 + k0r) * NDIM + n0r);
        float4 vb1 = *(const float4*)(F + (size_t)(k0 + k1r) * NDIM + n1r);
        __syncthreads();
        *(float2*)&Asd[c0c + 0][2 * r0c] = make_float2(va0.x, va0.x);
        *(float2*)&Asd[c0c + 1][2 * r0c] = make_float2(va0.y, va0.y);
        *(float2*)&Asd[c0c + 2][2 * r0c] = make_float2(va0.z, va0.z);
        *(float2*)&Asd[c0c + 3][2 * r0c] = make_float2(va0.w, va0.w);
        *(float2*)&Asd[c1c + 0][2 * r1c] = make_float2(va1.x, va1.x);
        *(float2*)&Asd[c1c + 1][2 * r1c] = make_float2(va1.y, va1.y);
        *(float2*)&Asd[c1c + 2][2 * r1c] = make_float2(va1.z, va1.z);
        *(float2*)&Asd[c1c + 3][2 * r1c] = make_float2(va1.w, va1.w);
        *(float4*)&Bs[k0r][n0r] = vb0;
        *(float4*)&Bs[k1r][n1r] = vb1;
        __syncthreads();
        mma_tile(Asd, Bs, m0, n0, acc);
    }

    const float beta0 = beta[0];
    const size_t obase = (size_t)b * CDIM * NDIM + (size_t)mblk * BM * NDIM
                       + (size_t)nblk * BM;
#pragma unroll
    for (int m = 0; m < 8; m++) {
        float v[8];
        unpack2(acc[m][0], v[0], v[1]);
        unpack2(acc[m][1], v[2], v[3]);
        unpack2(acc[m][2], v[4], v[5]);
        unpack2(acc[m][3], v[6], v[7]);
        const size_t off = obase + (size_t)(m0 + m) * NDIM + n0;
        const float4* xr = (const float4*)(x + off);
        float4 x0 = xr[0], x1 = xr[1];
        float4* o4 = (float4*)(out + off);
        o4[0] = make_float4(fmaf(beta0, v[0], x0.x), fmaf(beta0, v[1], x0.y),
                            fmaf(beta0, v[2], x0.z), fmaf(beta0, v[3], x0.w));
        o4[1] = make_float4(fmaf(beta0, v[4], x1.x), fmaf(beta0, v[5], x1.y),
                            fmaf(beta0, v[6], x1.z), fmaf(beta0, v[7], x1.w));
    }
}

// ---------------------------------------------------------------------------
extern "C" void kernel_launch(void* const* d_in, const int* in_sizes, int n_in,
                              void* d_out, int out_size) {
    (void)n_in; (void)out_size;
    const float* x    = (const float*)d_in[0];
    const float* beta = (const float*)d_in[1];
    if (in_sizes[0] == 1) {  // defensive: metadata order beta,x
        const float* tmp = x; x = beta; beta = tmp;
    }
    float* out = (float*)d_out;

    gram_kernel<<<dim3(10, BDIM), 256>>>(x);
    softmin_kernel<<<dim3(CDIM, BDIM), 128>>>();
    av_kernel<<<dim3(NDIM / BM, CDIM / BM, BDIM), 256>>>(x, beta, out);
}

// round 8
// speedup vs baseline: 3.2482x; 3.2482x over previous
#include <cuda_runtime.h>
#include <cuda_bf16.h>
#include <cstdint>

// ===========================================================================
// ChannelAttentionModule (DANet), B=32, C=512, N=H*W=1024, fp32.
//   S = feat @ feat^T ; W = softmax(rowmax(S)-S) = exp(rowmin-S)/sum ;
//   out = beta * (W @ feat) + x
// R8: tensor cores via ARCH-GENERIC path (ldmatrix + mma.sync bf16 ->
// f32 accum, HMMA). tcgen05 is rejected by this bench's compute_103 PTX
// target (R7 evidence). Precision: bf16 hi/lo 3-term split as 3 K-sections
// of one GEMM loop (drops only lo*lo, ~1e-4 rel err).
// ===========================================================================

#define BDIM 32
#define CDIM 512
#define NDIM 1024
#define LDSS 40                   // smem row stride in bf16 (32 + 8 pad)

// ---------------- scratch (static device globals: allowed) ----------------
__device__ float          g_scores[(size_t)BDIM * CDIM * CDIM];
__device__ __align__(16) unsigned short g_h [(size_t)BDIM * CDIM * NDIM]; // x hi  [b][c][n]
__device__ __align__(16) unsigned short g_l [(size_t)BDIM * CDIM * NDIM]; // x lo  [b][c][n]
__device__ __align__(16) unsigned short g_th[(size_t)BDIM * NDIM * CDIM]; // x^T hi [b][n][c]
__device__ __align__(16) unsigned short g_tl[(size_t)BDIM * NDIM * CDIM]; // x^T lo [b][n][c]
__device__ __align__(16) unsigned short g_wh[(size_t)BDIM * CDIM * CDIM]; // W hi  [b][c][d]
__device__ __align__(16) unsigned short g_wl[(size_t)BDIM * CDIM * CDIM]; // W lo  [b][c][d]

// ---------------- helpers ---------------------------------------------------
__device__ __forceinline__ uint32_t smem_u32(const void* p) {
    uint32_t a;
    asm("{ .reg .u64 t; cvta.to.shared.u64 t, %1; cvt.u32.u64 %0, t; }"
        : "=r"(a) : "l"(p));
    return a;
}
__device__ __forceinline__ void ldsm4(uint32_t r[4], uint32_t addr) {
    asm volatile("ldmatrix.sync.aligned.m8n8.x4.shared.b16 {%0,%1,%2,%3}, [%4];"
                 : "=r"(r[0]), "=r"(r[1]), "=r"(r[2]), "=r"(r[3]) : "r"(addr));
}
__device__ __forceinline__ void mma16816(float d[4], const uint32_t a[4],
                                         const uint32_t b[2]) {
    asm volatile(
        "mma.sync.aligned.m16n8k16.row.col.f32.bf16.bf16.f32 "
        "{%0,%1,%2,%3}, {%4,%5,%6,%7}, {%8,%9}, {%0,%1,%2,%3};"
        : "+f"(d[0]), "+f"(d[1]), "+f"(d[2]), "+f"(d[3])
        : "r"(a[0]), "r"(a[1]), "r"(a[2]), "r"(a[3]), "r"(b[0]), "r"(b[1]));
}
__device__ __forceinline__ void bsplit(float v, unsigned short& h, unsigned short& l) {
    __nv_bfloat16 hh = __float2bfloat16_rn(v);
    float r = v - __bfloat162float(hh);
    __nv_bfloat16 ll = __float2bfloat16_rn(r);
    h = *reinterpret_cast<unsigned short*>(&hh);
    l = *reinterpret_cast<unsigned short*>(&ll);
}

// ===========================================================================
// Shared 128x128 GEMM mainloop.  M=N=128, 256 threads, 8 warps (2M x 4N),
// warp tile 64x32, BK=32, double-buffered smem, 3 K-sections (hi/lo terms).
// A: [128][LD] row-major (K contig). B: [128][LD] row-major (= col-major KxN).
// acc[mi][ni][4] = 16 m16n8 fragments per thread's warp position.
// ===========================================================================
template <int KS, int NIT, int LD>
__device__ __forceinline__ void gemm_loop(
    const unsigned short* const* Asec, const unsigned short* const* Bsec,
    unsigned short (*As)[128 * LDSS], unsigned short (*Bs)[128 * LDSS],
    float acc[4][4][4])
{
    const int t = threadIdx.x, lane = t & 31, wid = t >> 5;
    const int lrow = t >> 2, lcol = (t & 3) * 8;        // global/smem copy map
    const int wm = (wid & 1) * 64, wn = (wid >> 1) * 32;

    { // first tile direct
        uint4 a0 = *(const uint4*)(Asec[0] + (size_t)lrow * LD + lcol);
        uint4 a1 = *(const uint4*)(Asec[0] + (size_t)(lrow + 64) * LD + lcol);
        uint4 b0 = *(const uint4*)(Bsec[0] + (size_t)lrow * LD + lcol);
        uint4 b1 = *(const uint4*)(Bsec[0] + (size_t)(lrow + 64) * LD + lcol);
        *(uint4*)&As[0][lrow * LDSS + lcol] = a0;
        *(uint4*)&As[0][(lrow + 64) * LDSS + lcol] = a1;
        *(uint4*)&Bs[0][lrow * LDSS + lcol] = b0;
        *(uint4*)&Bs[0][(lrow + 64) * LDSS + lcol] = b1;
    }
    __syncthreads();

    // ldmatrix per-lane address components
    const int a_r = wm + (lane & 15), a_k = (lane >> 4) * 8;
    const int b_r = wn + (lane & 7) + ((lane >> 4) << 3), b_k = (lane & 8);

    for (int it = 0; it < NIT; ++it) {
        const int cur = it & 1;
        uint4 pa0, pa1, pb0, pb1;
        const bool more = (it + 1 < NIT);
        if (more) {
            const int itn = it + 1;
            const int sec = itn / KS;
            const int ko  = (itn - sec * KS) * 32;
            const unsigned short* Ap = Asec[sec];
            const unsigned short* Bp = Bsec[sec];
            pa0 = *(const uint4*)(Ap + (size_t)lrow * LD + ko + lcol);
            pa1 = *(const uint4*)(Ap + (size_t)(lrow + 64) * LD + ko + lcol);
            pb0 = *(const uint4*)(Bp + (size_t)lrow * LD + ko + lcol);
            pb1 = *(const uint4*)(Bp + (size_t)(lrow + 64) * LD + ko + lcol);
        }
        const uint32_t ab = smem_u32(&As[cur][0]);
        const uint32_t bb = smem_u32(&Bs[cur][0]);
#pragma unroll
        for (int kk = 0; kk < 32; kk += 16) {
            uint32_t af[4][4], bf[2][4];
#pragma unroll
            for (int mi = 0; mi < 4; mi++)
                ldsm4(af[mi], ab + (uint32_t)(((a_r + 16 * mi) * LDSS) + kk + a_k) * 2);
#pragma unroll
            for (int nj = 0; nj < 2; nj++)
                ldsm4(bf[nj], bb + (uint32_t)(((b_r + 16 * nj) * LDSS) + kk + b_k) * 2);
#pragma unroll
            for (int mi = 0; mi < 4; mi++)
#pragma unroll
                for (int ni = 0; ni < 4; ni++)
                    mma16816(acc[mi][ni], af[mi], &bf[ni >> 1][(ni & 1) * 2]);
        }
        if (more) {
            const int nxt = cur ^ 1;
            *(uint4*)&As[nxt][lrow * LDSS + lcol] = pa0;
            *(uint4*)&As[nxt][(lrow + 64) * LDSS + lcol] = pa1;
            *(uint4*)&Bs[nxt][lrow * LDSS + lcol] = pb0;
            *(uint4*)&Bs[nxt][(lrow + 64) * LDSS + lcol] = pb1;
        }
        __syncthreads();
    }
}

// ===========================================================================
// Stage 0: split + transpose:  x -> g_h/g_l ([c][n])  and  g_th/g_tl ([n][c])
// ===========================================================================
__global__ void prep_kernel(const float* __restrict__ x) {
    const int b = blockIdx.z, c0 = blockIdx.y * 32, n0 = blockIdx.x * 32;
    __shared__ float tile[32][33];
    const int t = threadIdx.x;
    const int i = t >> 3, j0 = (t & 7) * 4;

    const size_t src = ((size_t)(b * CDIM + c0 + i) * NDIM) + n0 + j0;
    float4 v = *(const float4*)(x + src);
    tile[i][j0 + 0] = v.x; tile[i][j0 + 1] = v.y;
    tile[i][j0 + 2] = v.z; tile[i][j0 + 3] = v.w;

    unsigned short h[4], l[4];
    bsplit(v.x, h[0], l[0]); bsplit(v.y, h[1], l[1]);
    bsplit(v.z, h[2], l[2]); bsplit(v.w, h[3], l[3]);
    uint2 ph, pl;
    ph.x = h[0] | ((uint32_t)h[1] << 16); ph.y = h[2] | ((uint32_t)h[3] << 16);
    pl.x = l[0] | ((uint32_t)l[1] << 16); pl.y = l[2] | ((uint32_t)l[3] << 16);
    *(uint2*)(g_h + src) = ph;
    *(uint2*)(g_l + src) = pl;

    __syncthreads();

    float f0 = tile[j0 + 0][i], f1 = tile[j0 + 1][i];
    float f2 = tile[j0 + 2][i], f3 = tile[j0 + 3][i];
    bsplit(f0, h[0], l[0]); bsplit(f1, h[1], l[1]);
    bsplit(f2, h[2], l[2]); bsplit(f3, h[3], l[3]);
    ph.x = h[0] | ((uint32_t)h[1] << 16); ph.y = h[2] | ((uint32_t)h[3] << 16);
    pl.x = l[0] | ((uint32_t)l[1] << 16); pl.y = l[2] | ((uint32_t)l[3] << 16);
    const size_t dst = ((size_t)(b * NDIM + n0 + i) * CDIM) + c0 + j0;
    *(uint2*)(g_th + dst) = ph;
    *(uint2*)(g_tl + dst) = pl;
}

// ===========================================================================
// Stage 1: Gram S = F F^T via mma.sync. 10 upper-tri 128x128 tile pairs,
// mirrored on write. K = 1024 per section, 3 sections -> NIT = 96.
// ===========================================================================
__global__ __launch_bounds__(256)
void gram_mma() {
    __shared__ unsigned short As[2][128 * LDSS];
    __shared__ unsigned short Bs[2][128 * LDSS];

    const int b = blockIdx.y;
    int p = blockIdx.x;
    int ti = 0;
    while (p >= 4 - ti) { p -= 4 - ti; ti++; }
    const int tj = ti + p;

    const unsigned short* Ah = g_h + (size_t)(b * CDIM + ti * 128) * NDIM;
    const unsigned short* Al = g_l + (size_t)(b * CDIM + ti * 128) * NDIM;
    const unsigned short* Bh = g_h + (size_t)(b * CDIM + tj * 128) * NDIM;
    const unsigned short* Bl = g_l + (size_t)(b * CDIM + tj * 128) * NDIM;
    const unsigned short* Asec[3] = { Ah, Al, Ah };
    const unsigned short* Bsec[3] = { Bh, Bh, Bl };

    float acc[4][4][4];
#pragma unroll
    for (int i = 0; i < 4; i++)
#pragma unroll
        for (int j = 0; j < 4; j++)
#pragma unroll
            for (int k = 0; k < 4; k++) acc[i][j][k] = 0.f;

    gemm_loop<32, 96, NDIM>(Asec, Bsec, As, Bs, acc);

    const int lane = threadIdx.x & 31, wid = threadIdx.x >> 5;
    const int wm = (wid & 1) * 64, wn = (wid >> 1) * 32;
    float* Cb = g_scores + (size_t)b * CDIM * CDIM;
    const int r0 = ti * 128 + wm + (lane >> 2);
    const int c0 = tj * 128 + wn + 2 * (lane & 3);
#pragma unroll
    for (int mi = 0; mi < 4; mi++)
#pragma unroll
        for (int ni = 0; ni < 4; ni++) {
            const float* d = acc[mi][ni];
            const int gr = r0 + 16 * mi, gc = c0 + 8 * ni;
            *(float2*)&Cb[(size_t)gr * CDIM + gc]       = make_float2(d[0], d[1]);
            *(float2*)&Cb[(size_t)(gr + 8) * CDIM + gc] = make_float2(d[2], d[3]);
            if (ti != tj) {
                Cb[(size_t)gc * CDIM + gr]           = d[0];
                Cb[(size_t)(gc + 1) * CDIM + gr]     = d[1];
                Cb[(size_t)gc * CDIM + gr + 8]       = d[2];
                Cb[(size_t)(gc + 1) * CDIM + gr + 8] = d[3];
            }
        }
}

// ===========================================================================
// Stage 2: softmin rows of S -> bf16 hi/lo weights.
// ===========================================================================
__global__ void softmin_kernel() {
    const int b = blockIdx.y, r = blockIdx.x;
    const float* row = g_scores + ((size_t)b * CDIM + r) * CDIM;
    const int t = threadIdx.x;
    const int warp = t >> 5, lane = t & 31;

    float4 v = ((const float4*)row)[t];
    float mn = fminf(fminf(v.x, v.y), fminf(v.z, v.w));
#pragma unroll
    for (int o = 16; o > 0; o >>= 1)
        mn = fminf(mn, __shfl_xor_sync(0xffffffffu, mn, o));

    __shared__ float rmin[4], rsum[4];
    if (lane == 0) rmin[warp] = mn;
    __syncthreads();
    mn = fminf(fminf(rmin[0], rmin[1]), fminf(rmin[2], rmin[3]));

    float4 e;
    e.x = __expf(mn - v.x); e.y = __expf(mn - v.y);
    e.z = __expf(mn - v.z); e.w = __expf(mn - v.w);
    float s = e.x + e.y + e.z + e.w;
#pragma unroll
    for (int o = 16; o > 0; o >>= 1)
        s += __shfl_xor_sync(0xffffffffu, s, o);
    if (lane == 0) rsum[warp] = s;
    __syncthreads();
    s = rsum[0] + rsum[1] + rsum[2] + rsum[3];

    const float inv = __frcp_rn(s);
    unsigned short h[4], l[4];
    bsplit(e.x * inv, h[0], l[0]); bsplit(e.y * inv, h[1], l[1]);
    bsplit(e.z * inv, h[2], l[2]); bsplit(e.w * inv, h[3], l[3]);
    uint2 ph, pl;
    ph.x = h[0] | ((uint32_t)h[1] << 16); ph.y = h[2] | ((uint32_t)h[3] << 16);
    pl.x = l[0] | ((uint32_t)l[1] << 16); pl.y = l[2] | ((uint32_t)l[3] << 16);
    const size_t off = ((size_t)b * CDIM + r) * CDIM + t * 4;
    *(uint2*)(g_wh + off) = ph;
    *(uint2*)(g_wl + off) = pl;
}

// ===========================================================================
// Stage 3: out = beta * (W @ feat) + x via mma.sync.
// M = channels (W rows), N = spatial, K = 512 per section, NIT = 48.
// A = W [c][d] hi/lo, B = feat^T [n][c] hi/lo.
// ===========================================================================
__global__ __launch_bounds__(256)
void av_mma(const float* __restrict__ x, const float* __restrict__ beta,
            float* __restrict__ out) {
    __shared__ unsigned short As[2][128 * LDSS];
    __shared__ unsigned short Bs[2][128 * LDSS];

    const int b = blockIdx.z, nblk = blockIdx.x, mblk = blockIdx.y;

    const unsigned short* Wh = g_wh + (size_t)(b * CDIM + mblk * 128) * CDIM;
    const unsigned short* Wl = g_wl + (size_t)(b * CDIM + mblk * 128) * CDIM;
    const unsigned short* Fh = g_th + (size_t)(b * NDIM + nblk * 128) * CDIM;
    const unsigned short* Fl = g_tl + (size_t)(b * NDIM + nblk * 128) * CDIM;
    const unsigned short* Asec[3] = { Wh, Wl, Wh };
    const unsigned short* Bsec[3] = { Fh, Fh, Fl };

    float acc[4][4][4];
#pragma unroll
    for (int i = 0; i < 4; i++)
#pragma unroll
        for (int j = 0; j < 4; j++)
#pragma unroll
            for (int k = 0; k < 4; k++) acc[i][j][k] = 0.f;

    gemm_loop<16, 48, CDIM>(Asec, Bsec, As, Bs, acc);

    const int lane = threadIdx.x & 31, wid = threadIdx.x >> 5;
    const int wm = (wid & 1) * 64, wn = (wid >> 1) * 32;
    const float beta0 = beta[0];
    const int r0 = mblk * 128 + wm + (lane >> 2);   // channel
    const int c0 = nblk * 128 + wn + 2 * (lane & 3); // spatial
#pragma unroll
    for (int mi = 0; mi < 4; mi++)
#pragma unroll
        for (int ni = 0; ni < 4; ni++) {
            const float* d = acc[mi][ni];
            const int gr = r0 + 16 * mi, gc = c0 + 8 * ni;
            const size_t o0 = ((size_t)(b * CDIM + gr) * NDIM) + gc;
            const size_t o1 = ((size_t)(b * CDIM + gr + 8) * NDIM) + gc;
            float2 x0 = *(const float2*)(x + o0);
            float2 x1 = *(const float2*)(x + o1);
            *(float2*)(out + o0) = make_float2(fmaf(beta0, d[0], x0.x),
                                               fmaf(beta0, d[1], x0.y));
            *(float2*)(out + o1) = make_float2(fmaf(beta0, d[2], x1.x),
                                               fmaf(beta0, d[3], x1.y));
        }
}

// ===========================================================================
extern "C" void kernel_launch(void* const* d_in, const int* in_sizes, int n_in,
                              void* d_out, int out_size) {
    (void)n_in; (void)out_size;
    const float* x    = (const float*)d_in[0];
    const float* beta = (const float*)d_in[1];
    if (in_sizes[0] == 1) { const float* tmp = x; x = beta; beta = tmp; }
    float* out = (float*)d_out;

    prep_kernel<<<dim3(NDIM / 32, CDIM / 32, BDIM), 256>>>(x);
    gram_mma<<<dim3(10, BDIM), 256>>>();
    softmin_kernel<<<dim3(CDIM, BDIM), 128>>>();
    av_mma<<<dim3(NDIM / 128, CDIM / 128, BDIM), 256>>>(x, beta, out);
}

// round 9
// speedup vs baseline: 3.3084x; 1.0185x over previous
#include <cuda_runtime.h>
#include <cuda_bf16.h>
#include <cstdint>

// ===========================================================================
// ChannelAttentionModule (DANet), B=32, C=512, N=H*W=1024, fp32.
//   S = feat @ feat^T ; W = softmax(rowmax(S)-S) = exp(rowmin-S)/sum ;
//   out = beta * (W @ feat) + x
// R9: fused 3-term hi/lo GEMM — per K-chunk load Ah/Al/Bh/Bl ONCE and run
// all three MMA terms from them (was: 3 separate K-sections => 3x operand
// traffic). cp.async.cg for gmem->smem. 48B smem rows: conflict-free
// ldmatrix without the 80B padding. All PTX arch-generic (sm_80 class).
// ===========================================================================

#define BDIM 32
#define CDIM 512
#define NDIM 1024
#define LDSS 24                    // row stride in shorts (16 data + 8 pad = 48B)
#define TSZ  (128 * LDSS)          // shorts per 128x16 tile

// ---------------- scratch (static device globals: allowed) ----------------
__device__ float          g_scores[(size_t)BDIM * CDIM * CDIM];
__device__ __align__(16) unsigned short g_h [(size_t)BDIM * CDIM * NDIM]; // x hi  [b][c][n]
__device__ __align__(16) unsigned short g_l [(size_t)BDIM * CDIM * NDIM]; // x lo
__device__ __align__(16) unsigned short g_th[(size_t)BDIM * NDIM * CDIM]; // x^T hi [b][n][c]
__device__ __align__(16) unsigned short g_tl[(size_t)BDIM * NDIM * CDIM]; // x^T lo
__device__ __align__(16) unsigned short g_wh[(size_t)BDIM * CDIM * CDIM]; // W hi  [b][c][d]
__device__ __align__(16) unsigned short g_wl[(size_t)BDIM * CDIM * CDIM]; // W lo

// ---------------- helpers ---------------------------------------------------
__device__ __forceinline__ uint32_t smem_u32(const void* p) {
    uint32_t a;
    asm("{ .reg .u64 t; cvta.to.shared.u64 t, %1; cvt.u32.u64 %0, t; }"
        : "=r"(a) : "l"(p));
    return a;
}
__device__ __forceinline__ void ldsm4(uint32_t r[4], uint32_t addr) {
    asm volatile("ldmatrix.sync.aligned.m8n8.x4.shared.b16 {%0,%1,%2,%3}, [%4];"
                 : "=r"(r[0]), "=r"(r[1]), "=r"(r[2]), "=r"(r[3]) : "r"(addr));
}
__device__ __forceinline__ void mma16816(float d[4], const uint32_t a[4],
                                         const uint32_t b[2]) {
    asm volatile(
        "mma.sync.aligned.m16n8k16.row.col.f32.bf16.bf16.f32 "
        "{%0,%1,%2,%3}, {%4,%5,%6,%7}, {%8,%9}, {%0,%1,%2,%3};"
        : "+f"(d[0]), "+f"(d[1]), "+f"(d[2]), "+f"(d[3])
        : "r"(a[0]), "r"(a[1]), "r"(a[2]), "r"(a[3]), "r"(b[0]), "r"(b[1]));
}
__device__ __forceinline__ void cpa(uint32_t s, const void* g) {
    asm volatile("cp.async.cg.shared.global [%0], [%1], 16;" :: "r"(s), "l"(g));
}
#define CPC()  asm volatile("cp.async.commit_group;" ::: "memory")
#define CPW(n) asm volatile("cp.async.wait_group %0;" :: "n"(n) : "memory")

__device__ __forceinline__ void bsplit(float v, unsigned short& h, unsigned short& l) {
    __nv_bfloat16 hh = __float2bfloat16_rn(v);
    float r = v - __bfloat162float(hh);
    __nv_bfloat16 ll = __float2bfloat16_rn(r);
    h = *reinterpret_cast<unsigned short*>(&hh);
    l = *reinterpret_cast<unsigned short*>(&ll);
}

// ===========================================================================
// Fused 3-term 128x128 GEMM mainloop.
// 256 threads, 8 warps (2M x 4N), warp tile 64x32, K-chunk = 16.
// Per chunk: cp.async Ah/Al/Bh/Bl (once) -> 12 ldsm -> 48 MMAs
// (AhBh + AhBl + AlBh), double-buffered 2-stage cp.async pipeline.
// ===========================================================================
template <int NC, int LD>
__device__ __forceinline__ void gemm3(
    const unsigned short* __restrict__ Ah, const unsigned short* __restrict__ Al,
    const unsigned short* __restrict__ Bh, const unsigned short* __restrict__ Bl,
    unsigned short (*S)[4][TSZ],            // [2][4][TSZ]
    float acc[4][4][4])
{
    const int t = threadIdx.x, lane = t & 31, wid = t >> 5;
    // copy map: thread -> (row 0..127, col 0 or 8); warp-uniform col
    const int crow = t & 127, ccol = (t >> 7) * 8;
    const size_t goff = (size_t)crow * LD + ccol;
    const uint32_t soff = (uint32_t)(crow * LDSS + ccol) * 2;   // bytes

    const int wm = (wid & 1) * 64, wn = (wid >> 1) * 32;
    const int a_r = wm + (lane & 15), a_k = (lane >> 4) * 8;
    const int b_r = wn + (lane & 7) + ((lane >> 4) << 3), b_k = lane & 8;

    const unsigned short* src[4] = { Ah, Al, Bh, Bl };

    // prologue: chunk 0
#pragma unroll
    for (int tau = 0; tau < 4; tau++)
        cpa(smem_u32(&S[0][tau][0]) + soff, src[tau] + goff);
    CPC();

    for (int c = 0; c < NC; c++) {
        if (c + 1 < NC) {
            const int nb = (c + 1) & 1;
            const size_t go = goff + (size_t)(c + 1) * 16;
#pragma unroll
            for (int tau = 0; tau < 4; tau++)
                cpa(smem_u32(&S[nb][tau][0]) + soff, src[tau] + go);
            CPC();
            CPW(1);
        } else {
            CPW(0);
        }
        __syncthreads();

        const int cb = c & 1;
        const uint32_t bAh = smem_u32(&S[cb][0][0]);
        const uint32_t bAl = smem_u32(&S[cb][1][0]);
        const uint32_t bBh = smem_u32(&S[cb][2][0]);
        const uint32_t bBl = smem_u32(&S[cb][3][0]);

        uint32_t AhF[4][4], AlF[4][4], BhF[2][4], BlF[2][4];
#pragma unroll
        for (int mi = 0; mi < 4; mi++)
            ldsm4(AhF[mi], bAh + (uint32_t)(((a_r + 16 * mi) * LDSS) + a_k) * 2);
#pragma unroll
        for (int nj = 0; nj < 2; nj++)
            ldsm4(BhF[nj], bBh + (uint32_t)(((b_r + 16 * nj) * LDSS) + b_k) * 2);
        // term 1: Ah x Bh
#pragma unroll
        for (int mi = 0; mi < 4; mi++)
#pragma unroll
            for (int ni = 0; ni < 4; ni++)
                mma16816(acc[mi][ni], AhF[mi], &BhF[ni >> 1][(ni & 1) * 2]);
        // term 3: Ah x Bl
#pragma unroll
        for (int nj = 0; nj < 2; nj++)
            ldsm4(BlF[nj], bBl + (uint32_t)(((b_r + 16 * nj) * LDSS) + b_k) * 2);
#pragma unroll
        for (int mi = 0; mi < 4; mi++)
#pragma unroll
            for (int ni = 0; ni < 4; ni++)
                mma16816(acc[mi][ni], AhF[mi], &BlF[ni >> 1][(ni & 1) * 2]);
        // term 2: Al x Bh   (AhF dead -> registers recycled)
#pragma unroll
        for (int mi = 0; mi < 4; mi++)
            ldsm4(AlF[mi], bAl + (uint32_t)(((a_r + 16 * mi) * LDSS) + a_k) * 2);
#pragma unroll
        for (int mi = 0; mi < 4; mi++)
#pragma unroll
            for (int ni = 0; ni < 4; ni++)
                mma16816(acc[mi][ni], AlF[mi], &BhF[ni >> 1][(ni & 1) * 2]);

        __syncthreads();
    }
}

// ===========================================================================
// Stage 0: split + transpose:  x -> g_h/g_l ([c][n])  and  g_th/g_tl ([n][c])
// ===========================================================================
__global__ void prep_kernel(const float* __restrict__ x) {
    const int b = blockIdx.z, c0 = blockIdx.y * 32, n0 = blockIdx.x * 32;
    __shared__ float tile[32][33];
    const int t = threadIdx.x;
    const int i = t >> 3, j0 = (t & 7) * 4;

    const size_t src = ((size_t)(b * CDIM + c0 + i) * NDIM) + n0 + j0;
    float4 v = *(const float4*)(x + src);
    tile[i][j0 + 0] = v.x; tile[i][j0 + 1] = v.y;
    tile[i][j0 + 2] = v.z; tile[i][j0 + 3] = v.w;

    unsigned short h[4], l[4];
    bsplit(v.x, h[0], l[0]); bsplit(v.y, h[1], l[1]);
    bsplit(v.z, h[2], l[2]); bsplit(v.w, h[3], l[3]);
    uint2 ph, pl;
    ph.x = h[0] | ((uint32_t)h[1] << 16); ph.y = h[2] | ((uint32_t)h[3] << 16);
    pl.x = l[0] | ((uint32_t)l[1] << 16); pl.y = l[2] | ((uint32_t)l[3] << 16);
    *(uint2*)(g_h + src) = ph;
    *(uint2*)(g_l + src) = pl;

    __syncthreads();

    float f0 = tile[j0 + 0][i], f1 = tile[j0 + 1][i];
    float f2 = tile[j0 + 2][i], f3 = tile[j0 + 3][i];
    bsplit(f0, h[0], l[0]); bsplit(f1, h[1], l[1]);
    bsplit(f2, h[2], l[2]); bsplit(f3, h[3], l[3]);
    ph.x = h[0] | ((uint32_t)h[1] << 16); ph.y = h[2] | ((uint32_t)h[3] << 16);
    pl.x = l[0] | ((uint32_t)l[1] << 16); pl.y = l[2] | ((uint32_t)l[3] << 16);
    const size_t dst = ((size_t)(b * NDIM + n0 + i) * CDIM) + c0 + j0;
    *(uint2*)(g_th + dst) = ph;
    *(uint2*)(g_tl + dst) = pl;
}

// ===========================================================================
// Stage 1: Gram S = F F^T. 10 upper-tri 128x128 tile pairs, mirrored.
// NC = 1024/16 = 64 chunks.
// ===========================================================================
__global__ __launch_bounds__(256, 2)
void gram_mma() {
    __shared__ unsigned short S[2][4][TSZ];      // exactly 48 KB

    const int b = blockIdx.y;
    int p = blockIdx.x;
    int ti = 0;
    while (p >= 4 - ti) { p -= 4 - ti; ti++; }
    const int tj = ti + p;

    const unsigned short* Ah = g_h + (size_t)(b * CDIM + ti * 128) * NDIM;
    const unsigned short* Al = g_l + (size_t)(b * CDIM + ti * 128) * NDIM;
    const unsigned short* Bh = g_h + (size_t)(b * CDIM + tj * 128) * NDIM;
    const unsigned short* Bl = g_l + (size_t)(b * CDIM + tj * 128) * NDIM;

    float acc[4][4][4];
#pragma unroll
    for (int i = 0; i < 4; i++)
#pragma unroll
        for (int j = 0; j < 4; j++)
#pragma unroll
            for (int k = 0; k < 4; k++) acc[i][j][k] = 0.f;

    gemm3<64, NDIM>(Ah, Al, Bh, Bl, S, acc);

    const int lane = threadIdx.x & 31, wid = threadIdx.x >> 5;
    const int wm = (wid & 1) * 64, wn = (wid >> 1) * 32;
    float* Cb = g_scores + (size_t)b * CDIM * CDIM;
    const int r0 = ti * 128 + wm + (lane >> 2);
    const int c0 = tj * 128 + wn + 2 * (lane & 3);
#pragma unroll
    for (int mi = 0; mi < 4; mi++)
#pragma unroll
        for (int ni = 0; ni < 4; ni++) {
            const float* d = acc[mi][ni];
            const int gr = r0 + 16 * mi, gc = c0 + 8 * ni;
            *(float2*)&Cb[(size_t)gr * CDIM + gc]       = make_float2(d[0], d[1]);
            *(float2*)&Cb[(size_t)(gr + 8) * CDIM + gc] = make_float2(d[2], d[3]);
            if (ti != tj) {
                Cb[(size_t)gc * CDIM + gr]           = d[0];
                Cb[(size_t)(gc + 1) * CDIM + gr]     = d[1];
                Cb[(size_t)gc * CDIM + gr + 8]       = d[2];
                Cb[(size_t)(gc + 1) * CDIM + gr + 8] = d[3];
            }
        }
}

// ===========================================================================
// Stage 2: softmin rows of S -> bf16 hi/lo weights.
// ===========================================================================
__global__ void softmin_kernel() {
    const int b = blockIdx.y, r = blockIdx.x;
    const float* row = g_scores + ((size_t)b * CDIM + r) * CDIM;
    const int t = threadIdx.x;
    const int warp = t >> 5, lane = t & 31;

    float4 v = ((const float4*)row)[t];
    float mn = fminf(fminf(v.x, v.y), fminf(v.z, v.w));
#pragma unroll
    for (int o = 16; o > 0; o >>= 1)
        mn = fminf(mn, __shfl_xor_sync(0xffffffffu, mn, o));

    __shared__ float rmin[4], rsum[4];
    if (lane == 0) rmin[warp] = mn;
    __syncthreads();
    mn = fminf(fminf(rmin[0], rmin[1]), fminf(rmin[2], rmin[3]));

    float4 e;
    e.x = __expf(mn - v.x); e.y = __expf(mn - v.y);
    e.z = __expf(mn - v.z); e.w = __expf(mn - v.w);
    float s = e.x + e.y + e.z + e.w;
#pragma unroll
    for (int o = 16; o > 0; o >>= 1)
        s += __shfl_xor_sync(0xffffffffu, s, o);
    if (lane == 0) rsum[warp] = s;
    __syncthreads();
    s = rsum[0] + rsum[1] + rsum[2] + rsum[3];

    const float inv = __frcp_rn(s);
    unsigned short h[4], l[4];
    bsplit(e.x * inv, h[0], l[0]); bsplit(e.y * inv, h[1], l[1]);
    bsplit(e.z * inv, h[2], l[2]); bsplit(e.w * inv, h[3], l[3]);
    uint2 ph, pl;
    ph.x = h[0] | ((uint32_t)h[1] << 16); ph.y = h[2] | ((uint32_t)h[3] << 16);
    pl.x = l[0] | ((uint32_t)l[1] << 16); pl.y = l[2] | ((uint32_t)l[3] << 16);
    const size_t off = ((size_t)b * CDIM + r) * CDIM + t * 4;
    *(uint2*)(g_wh + off) = ph;
    *(uint2*)(g_wl + off) = pl;
}

// ===========================================================================
// Stage 3: out = beta * (W @ feat) + x.  NC = 512/16 = 32 chunks.
// A = W [c][d] hi/lo, B = feat^T [n][c] hi/lo.
// ===========================================================================
__global__ __launch_bounds__(256, 2)
void av_mma(const float* __restrict__ x, const float* __restrict__ beta,
            float* __restrict__ out) {
    __shared__ unsigned short S[2][4][TSZ];      // exactly 48 KB

    const int b = blockIdx.z, nblk = blockIdx.x, mblk = blockIdx.y;

    const unsigned short* Wh = g_wh + (size_t)(b * CDIM + mblk * 128) * CDIM;
    const unsigned short* Wl = g_wl + (size_t)(b * CDIM + mblk * 128) * CDIM;
    const unsigned short* Fh = g_th + (size_t)(b * NDIM + nblk * 128) * CDIM;
    const unsigned short* Fl = g_tl + (size_t)(b * NDIM + nblk * 128) * CDIM;

    float acc[4][4][4];
#pragma unroll
    for (int i = 0; i < 4; i++)
#pragma unroll
        for (int j = 0; j < 4; j++)
#pragma unroll
            for (int k = 0; k < 4; k++) acc[i][j][k] = 0.f;

    gemm3<32, CDIM>(Wh, Wl, Fh, Fl, S, acc);

    const int lane = threadIdx.x & 31, wid = threadIdx.x >> 5;
    const int wm = (wid & 1) * 64, wn = (wid >> 1) * 32;
    const float beta0 = beta[0];
    const int r0 = mblk * 128 + wm + (lane >> 2);     // channel
    const int c0 = nblk * 128 + wn + 2 * (lane & 3);  // spatial
#pragma unroll
    for (int mi = 0; mi < 4; mi++)
#pragma unroll
        for (int ni = 0; ni < 4; ni++) {
            const float* d = acc[mi][ni];
            const int gr = r0 + 16 * mi, gc = c0 + 8 * ni;
            const size_t o0 = ((size_t)(b * CDIM + gr) * NDIM) + gc;
            const size_t o1 = ((size_t)(b * CDIM + gr + 8) * NDIM) + gc;
            float2 x0 = *(const float2*)(x + o0);
            float2 x1 = *(const float2*)(x + o1);
            *(float2*)(out + o0) = make_float2(fmaf(beta0, d[0], x0.x),
                                               fmaf(beta0, d[1], x0.y));
            *(float2*)(out + o1) = make_float2(fmaf(beta0, d[2], x1.x),
                                               fmaf(beta0, d[3], x1.y));
        }
}

// ===========================================================================
extern "C" void kernel_launch(void* const* d_in, const int* in_sizes, int n_in,
                              void* d_out, int out_size) {
    (void)n_in; (void)out_size;
    const float* x    = (const float*)d_in[0];
    const float* beta = (const float*)d_in[1];
    if (in_sizes[0] == 1) { const float* tmp = x; x = beta; beta = tmp; }
    float* out = (float*)d_out;

    prep_kernel<<<dim3(NDIM / 32, CDIM / 32, BDIM), 256>>>(x);
    gram_mma<<<dim3(10, BDIM), 256>>>();
    softmin_kernel<<<dim3(CDIM, BDIM), 128>>>();
    av_mma<<<dim3(NDIM / 128, CDIM / 128, BDIM), 256>>>(x, beta, out);
}

// round 10
// speedup vs baseline: 4.1465x; 1.2533x over previous
#include <cuda_runtime.h>
#include <cuda_bf16.h>
#include <cstdint>

// ===========================================================================
// ChannelAttentionModule (DANet), B=32, C=512, N=H*W=1024, fp32.
//   S = feat @ feat^T ; W = softmax(rowmax(S)-S) = exp(rowmin-S)/sum ;
//   out = beta * (W @ feat) + x
// R10: latency fix for the fused 3-term hi/lo mma.sync GEMMs:
//   * 3-stage cp.async pipeline (prefetch distance 2 chunks)
//   * unpadded XOR-swizzled smem tiles (4KB/tile) -> 3 stages fit in 48KB
//   * ONE __syncthreads per K-chunk (was 2)
// ===========================================================================

#define BDIM 32
#define CDIM 512
#define NDIM 1024
#define TSZ  2048                  // shorts per 128x16 tile (no padding)

// ---------------- scratch (static device globals: allowed) ----------------
__device__ float          g_scores[(size_t)BDIM * CDIM * CDIM];
__device__ __align__(16) unsigned short g_h [(size_t)BDIM * CDIM * NDIM]; // x hi  [b][c][n]
__device__ __align__(16) unsigned short g_l [(size_t)BDIM * CDIM * NDIM]; // x lo
__device__ __align__(16) unsigned short g_th[(size_t)BDIM * NDIM * CDIM]; // x^T hi [b][n][c]
__device__ __align__(16) unsigned short g_tl[(size_t)BDIM * NDIM * CDIM]; // x^T lo
__device__ __align__(16) unsigned short g_wh[(size_t)BDIM * CDIM * CDIM]; // W hi  [b][c][d]
__device__ __align__(16) unsigned short g_wl[(size_t)BDIM * CDIM * CDIM]; // W lo

// ---------------- helpers ---------------------------------------------------
__device__ __forceinline__ uint32_t smem_u32(const void* p) {
    uint32_t a;
    asm("{ .reg .u64 t; cvta.to.shared.u64 t, %1; cvt.u32.u64 %0, t; }"
        : "=r"(a) : "l"(p));
    return a;
}
__device__ __forceinline__ void ldsm4(uint32_t r[4], uint32_t addr) {
    asm volatile("ldmatrix.sync.aligned.m8n8.x4.shared.b16 {%0,%1,%2,%3}, [%4];"
                 : "=r"(r[0]), "=r"(r[1]), "=r"(r[2]), "=r"(r[3]) : "r"(addr));
}
__device__ __forceinline__ void mma16816(float d[4], const uint32_t a[4],
                                         const uint32_t b[2]) {
    asm volatile(
        "mma.sync.aligned.m16n8k16.row.col.f32.bf16.bf16.f32 "
        "{%0,%1,%2,%3}, {%4,%5,%6,%7}, {%8,%9}, {%0,%1,%2,%3};"
        : "+f"(d[0]), "+f"(d[1]), "+f"(d[2]), "+f"(d[3])
        : "r"(a[0]), "r"(a[1]), "r"(a[2]), "r"(a[3]), "r"(b[0]), "r"(b[1]));
}
__device__ __forceinline__ void cpa(uint32_t s, const void* g) {
    asm volatile("cp.async.cg.shared.global [%0], [%1], 16;" :: "r"(s), "l"(g));
}
#define CPC()  asm volatile("cp.async.commit_group;" ::: "memory")
#define CPW(n) asm volatile("cp.async.wait_group %0;" :: "n"(n) : "memory")

// Tile-local byte offset for (row, k-half) with bank-conflict-free swizzle:
// row stride 32B, the two 16B k-halves swap every 4 rows.
__device__ __forceinline__ uint32_t tswz(int row, int kh) {
    return (uint32_t)(row * 32 + ((kh ^ ((row >> 2) & 1)) << 4));
}

__device__ __forceinline__ void bsplit(float v, unsigned short& h, unsigned short& l) {
    __nv_bfloat16 hh = __float2bfloat16_rn(v);
    float r = v - __bfloat162float(hh);
    __nv_bfloat16 ll = __float2bfloat16_rn(r);
    h = *reinterpret_cast<unsigned short*>(&hh);
    l = *reinterpret_cast<unsigned short*>(&ll);
}

// ===========================================================================
// Fused 3-term 128x128 GEMM mainloop, 3-stage cp.async pipeline.
// 256 threads, 8 warps (2M x 4N), warp tile 64x32, K-chunk = 16.
// Per chunk: 12 ldsm -> 48 MMAs (AhBh + AhBl + AlBh). One sync per chunk.
// ===========================================================================
template <int NC, int LD>
__device__ __forceinline__ void gemm3(
    const unsigned short* __restrict__ Ah, const unsigned short* __restrict__ Al,
    const unsigned short* __restrict__ Bh, const unsigned short* __restrict__ Bl,
    unsigned short (*S)[4][TSZ],            // [3][4][TSZ]
    float acc[4][4][4])
{
    const int t = threadIdx.x, lane = t & 31, wid = t >> 5;
    // copy map: thread -> (row 0..127, k-half 0/1), one 16B cp.async each
    const int crow = t >> 1, ckh = t & 1;
    const size_t goff = (size_t)crow * LD + ckh * 8;
    const uint32_t soff = tswz(crow, ckh);

    const int wm = (wid & 1) * 64, wn = (wid >> 1) * 32;
    const int a_r = wm + (lane & 15), a_kh = lane >> 4;
    const int b_r = wn + (lane & 7) + ((lane >> 4) << 3), b_kh = (lane >> 3) & 1;

    const unsigned short* src[4] = { Ah, Al, Bh, Bl };

    // prologue: chunks 0 and 1, separate commit groups
#pragma unroll
    for (int pc = 0; pc < 2; pc++) {
        if (pc < NC) {
#pragma unroll
            for (int tau = 0; tau < 4; tau++)
                cpa(smem_u32(&S[pc][tau][0]) + soff, src[tau] + goff + pc * 16);
            CPC();
        }
    }

    for (int c = 0; c < NC; c++) {
        if (c + 1 < NC) { CPW(1); } else { CPW(0); }
        __syncthreads();
        if (c + 2 < NC) {
            const int nb = (c + 2) % 3;
            const size_t go = goff + (size_t)(c + 2) * 16;
#pragma unroll
            for (int tau = 0; tau < 4; tau++)
                cpa(smem_u32(&S[nb][tau][0]) + soff, src[tau] + go);
            CPC();
        }

        const int cb = c % 3;
        const uint32_t bAh = smem_u32(&S[cb][0][0]);
        const uint32_t bAl = smem_u32(&S[cb][1][0]);
        const uint32_t bBh = smem_u32(&S[cb][2][0]);
        const uint32_t bBl = smem_u32(&S[cb][3][0]);

        uint32_t AhF[4][4], AlF[4][4], BhF[2][4], BlF[2][4];
#pragma unroll
        for (int mi = 0; mi < 4; mi++)
            ldsm4(AhF[mi], bAh + tswz(a_r + 16 * mi, a_kh));
#pragma unroll
        for (int nj = 0; nj < 2; nj++)
            ldsm4(BhF[nj], bBh + tswz(b_r + 16 * nj, b_kh));
        // term 1: Ah x Bh
#pragma unroll
        for (int mi = 0; mi < 4; mi++)
#pragma unroll
            for (int ni = 0; ni < 4; ni++)
                mma16816(acc[mi][ni], AhF[mi], &BhF[ni >> 1][(ni & 1) * 2]);
        // term 2: Ah x Bl
#pragma unroll
        for (int nj = 0; nj < 2; nj++)
            ldsm4(BlF[nj], bBl + tswz(b_r + 16 * nj, b_kh));
#pragma unroll
        for (int mi = 0; mi < 4; mi++)
#pragma unroll
            for (int ni = 0; ni < 4; ni++)
                mma16816(acc[mi][ni], AhF[mi], &BlF[ni >> 1][(ni & 1) * 2]);
        // term 3: Al x Bh
#pragma unroll
        for (int mi = 0; mi < 4; mi++)
            ldsm4(AlF[mi], bAl + tswz(a_r + 16 * mi, a_kh));
#pragma unroll
        for (int mi = 0; mi < 4; mi++)
#pragma unroll
            for (int ni = 0; ni < 4; ni++)
                mma16816(acc[mi][ni], AlF[mi], &BhF[ni >> 1][(ni & 1) * 2]);
        // NOTE: no trailing sync — next iteration's top sync covers reuse.
    }
}

// ===========================================================================
// Stage 0: split + transpose:  x -> g_h/g_l ([c][n])  and  g_th/g_tl ([n][c])
// ===========================================================================
__global__ void prep_kernel(const float* __restrict__ x) {
    const int b = blockIdx.z, c0 = blockIdx.y * 32, n0 = blockIdx.x * 32;
    __shared__ float tile[32][33];
    const int t = threadIdx.x;
    const int i = t >> 3, j0 = (t & 7) * 4;

    const size_t src = ((size_t)(b * CDIM + c0 + i) * NDIM) + n0 + j0;
    float4 v = *(const float4*)(x + src);
    tile[i][j0 + 0] = v.x; tile[i][j0 + 1] = v.y;
    tile[i][j0 + 2] = v.z; tile[i][j0 + 3] = v.w;

    unsigned short h[4], l[4];
    bsplit(v.x, h[0], l[0]); bsplit(v.y, h[1], l[1]);
    bsplit(v.z, h[2], l[2]); bsplit(v.w, h[3], l[3]);
    uint2 ph, pl;
    ph.x = h[0] | ((uint32_t)h[1] << 16); ph.y = h[2] | ((uint32_t)h[3] << 16);
    pl.x = l[0] | ((uint32_t)l[1] << 16); pl.y = l[2] | ((uint32_t)l[3] << 16);
    *(uint2*)(g_h + src) = ph;
    *(uint2*)(g_l + src) = pl;

    __syncthreads();

    float f0 = tile[j0 + 0][i], f1 = tile[j0 + 1][i];
    float f2 = tile[j0 + 2][i], f3 = tile[j0 + 3][i];
    bsplit(f0, h[0], l[0]); bsplit(f1, h[1], l[1]);
    bsplit(f2, h[2], l[2]); bsplit(f3, h[3], l[3]);
    ph.x = h[0] | ((uint32_t)h[1] << 16); ph.y = h[2] | ((uint32_t)h[3] << 16);
    pl.x = l[0] | ((uint32_t)l[1] << 16); pl.y = l[2] | ((uint32_t)l[3] << 16);
    const size_t dst = ((size_t)(b * NDIM + n0 + i) * CDIM) + c0 + j0;
    *(uint2*)(g_th + dst) = ph;
    *(uint2*)(g_tl + dst) = pl;
}

// ===========================================================================
// Stage 1: Gram S = F F^T. 10 upper-tri 128x128 tile pairs, mirrored.
// NC = 1024/16 = 64 chunks.
// ===========================================================================
__global__ __launch_bounds__(256, 2)
void gram_mma() {
    __shared__ unsigned short S[3][4][TSZ];      // exactly 48 KB

    const int b = blockIdx.y;
    int p = blockIdx.x;
    int ti = 0;
    while (p >= 4 - ti) { p -= 4 - ti; ti++; }
    const int tj = ti + p;

    const unsigned short* Ah = g_h + (size_t)(b * CDIM + ti * 128) * NDIM;
    const unsigned short* Al = g_l + (size_t)(b * CDIM + ti * 128) * NDIM;
    const unsigned short* Bh = g_h + (size_t)(b * CDIM + tj * 128) * NDIM;
    const unsigned short* Bl = g_l + (size_t)(b * CDIM + tj * 128) * NDIM;

    float acc[4][4][4];
#pragma unroll
    for (int i = 0; i < 4; i++)
#pragma unroll
        for (int j = 0; j < 4; j++)
#pragma unroll
            for (int k = 0; k < 4; k++) acc[i][j][k] = 0.f;

    gemm3<64, NDIM>(Ah, Al, Bh, Bl, S, acc);

    const int lane = threadIdx.x & 31, wid = threadIdx.x >> 5;
    const int wm = (wid & 1) * 64, wn = (wid >> 1) * 32;
    float* Cb = g_scores + (size_t)b * CDIM * CDIM;
    const int r0 = ti * 128 + wm + (lane >> 2);
    const int c0 = tj * 128 + wn + 2 * (lane & 3);
#pragma unroll
    for (int mi = 0; mi < 4; mi++)
#pragma unroll
        for (int ni = 0; ni < 4; ni++) {
            const float* d = acc[mi][ni];
            const int gr = r0 + 16 * mi, gc = c0 + 8 * ni;
            *(float2*)&Cb[(size_t)gr * CDIM + gc]       = make_float2(d[0], d[1]);
            *(float2*)&Cb[(size_t)(gr + 8) * CDIM + gc] = make_float2(d[2], d[3]);
            if (ti != tj) {
                Cb[(size_t)gc * CDIM + gr]           = d[0];
                Cb[(size_t)(gc + 1) * CDIM + gr]     = d[1];
                Cb[(size_t)gc * CDIM + gr + 8]       = d[2];
                Cb[(size_t)(gc + 1) * CDIM + gr + 8] = d[3];
            }
        }
}

// ===========================================================================
// Stage 2: softmin rows of S -> bf16 hi/lo weights.
// ===========================================================================
__global__ void softmin_kernel() {
    const int b = blockIdx.y, r = blockIdx.x;
    const float* row = g_scores + ((size_t)b * CDIM + r) * CDIM;
    const int t = threadIdx.x;
    const int warp = t >> 5, lane = t & 31;

    float4 v = ((const float4*)row)[t];
    float mn = fminf(fminf(v.x, v.y), fminf(v.z, v.w));
#pragma unroll
    for (int o = 16; o > 0; o >>= 1)
        mn = fminf(mn, __shfl_xor_sync(0xffffffffu, mn, o));

    __shared__ float rmin[4], rsum[4];
    if (lane == 0) rmin[warp] = mn;
    __syncthreads();
    mn = fminf(fminf(rmin[0], rmin[1]), fminf(rmin[2], rmin[3]));

    float4 e;
    e.x = __expf(mn - v.x); e.y = __expf(mn - v.y);
    e.z = __expf(mn - v.z); e.w = __expf(mn - v.w);
    float s = e.x + e.y + e.z + e.w;
#pragma unroll
    for (int o = 16; o > 0; o >>= 1)
        s += __shfl_xor_sync(0xffffffffu, s, o);
    if (lane == 0) rsum[warp] = s;
    __syncthreads();
    s = rsum[0] + rsum[1] + rsum[2] + rsum[3];

    const float inv = __frcp_rn(s);
    unsigned short h[4], l[4];
    bsplit(e.x * inv, h[0], l[0]); bsplit(e.y * inv, h[1], l[1]);
    bsplit(e.z * inv, h[2], l[2]); bsplit(e.w * inv, h[3], l[3]);
    uint2 ph, pl;
    ph.x = h[0] | ((uint32_t)h[1] << 16); ph.y = h[2] | ((uint32_t)h[3] << 16);
    pl.x = l[0] | ((uint32_t)l[1] << 16); pl.y = l[2] | ((uint32_t)l[3] << 16);
    const size_t off = ((size_t)b * CDIM + r) * CDIM + t * 4;
    *(uint2*)(g_wh + off) = ph;
    *(uint2*)(g_wl + off) = pl;
}

// ===========================================================================
// Stage 3: out = beta * (W @ feat) + x.  NC = 512/16 = 32 chunks.
// A = W [c][d] hi/lo, B = feat^T [n][c] hi/lo.
// ===========================================================================
__global__ __launch_bounds__(256, 2)
void av_mma(const float* __restrict__ x, const float* __restrict__ beta,
            float* __restrict__ out) {
    __shared__ unsigned short S[3][4][TSZ];      // exactly 48 KB

    const int b = blockIdx.z, nblk = blockIdx.x, mblk = blockIdx.y;

    const unsigned short* Wh = g_wh + (size_t)(b * CDIM + mblk * 128) * CDIM;
    const unsigned short* Wl = g_wl + (size_t)(b * CDIM + mblk * 128) * CDIM;
    const unsigned short* Fh = g_th + (size_t)(b * NDIM + nblk * 128) * CDIM;
    const unsigned short* Fl = g_tl + (size_t)(b * NDIM + nblk * 128) * CDIM;

    float acc[4][4][4];
#pragma unroll
    for (int i = 0; i < 4; i++)
#pragma unroll
        for (int j = 0; j < 4; j++)
#pragma unroll
            for (int k = 0; k < 4; k++) acc[i][j][k] = 0.f;

    gemm3<32, CDIM>(Wh, Wl, Fh, Fl, S, acc);

    const int lane = threadIdx.x & 31, wid = threadIdx.x >> 5;
    const int wm = (wid & 1) * 64, wn = (wid >> 1) * 32;
    const float beta0 = beta[0];
    const int r0 = mblk * 128 + wm + (lane >> 2);     // channel
    const int c0 = nblk * 128 + wn + 2 * (lane & 3);  // spatial
#pragma unroll
    for (int mi = 0; mi < 4; mi++)
#pragma unroll
        for (int ni = 0; ni < 4; ni++) {
            const float* d = acc[mi][ni];
            const int gr = r0 + 16 * mi, gc = c0 + 8 * ni;
            const size_t o0 = ((size_t)(b * CDIM + gr) * NDIM) + gc;
            const size_t o1 = ((size_t)(b * CDIM + gr + 8) * NDIM) + gc;
            float2 x0 = *(const float2*)(x + o0);
            float2 x1 = *(const float2*)(x + o1);
            *(float2*)(out + o0) = make_float2(fmaf(beta0, d[0], x0.x),
                                               fmaf(beta0, d[1], x0.y));
            *(float2*)(out + o1) = make_float2(fmaf(beta0, d[2], x1.x),
                                               fmaf(beta0, d[3], x1.y));
        }
}

// ===========================================================================
extern "C" void kernel_launch(void* const* d_in, const int* in_sizes, int n_in,
                              void* d_out, int out_size) {
    (void)n_in; (void)out_size;
    const float* x    = (const float*)d_in[0];
    const float* beta = (const float*)d_in[1];
    if (in_sizes[0] == 1) { const float* tmp = x; x = beta; beta = tmp; }
    float* out = (float*)d_out;

    prep_kernel<<<dim3(NDIM / 32, CDIM / 32, BDIM), 256>>>(x);
    gram_mma<<<dim3(10, BDIM), 256>>>();
    softmin_kernel<<<dim3(CDIM, BDIM), 128>>>();
    av_mma<<<dim3(NDIM / 128, CDIM / 128, BDIM), 256>>>(x, beta, out);
}